// round 2
// baseline (speedup 1.0000x reference)
#include <cuda_runtime.h>

// Problem dims (fixed by dataset)
#define ND 1024   // N
#define KD 64     // K
#define BD 64     // batch
#define BO 4096   // B*K
#define NITER 20

// ---------------- scratch (device globals; no runtime alloc) ----------------
__device__ float g_P [ND * ND];   // exp(A_logits/T)
__device__ float g_Pt[ND * ND];   // transpose of g_P
__device__ float g_r [ND];        // row scalings
__device__ float g_c [ND];        // col scalings
__device__ float g_XL[ND * BO];   // c[n] * x_local, laid out [n][b*64+o]

// ---------------- 1) P = exp(5*L), plus transpose ----------------
__global__ __launch_bounds__(256) void exp_T_kernel(const float* __restrict__ L) {
    __shared__ float tile[32][33];
    int bx = blockIdx.x * 32, by = blockIdx.y * 32;
    int tx = threadIdx.x, ty = threadIdx.y;   // 32 x 8
#pragma unroll
    for (int r0 = 0; r0 < 32; r0 += 8) {
        float v = expf(5.0f * L[(by + ty + r0) * ND + bx + tx]);
        g_P[(by + ty + r0) * ND + bx + tx] = v;
        tile[ty + r0][tx] = v;
    }
    __syncthreads();
#pragma unroll
    for (int r0 = 0; r0 < 32; r0 += 8)
        g_Pt[(bx + ty + r0) * ND + by + tx] = tile[tx][ty + r0];
}

__global__ void init_c_kernel() {
    int i = blockIdx.x * 256 + threadIdx.x;
    if (i < ND) g_c[i] = 1.0f;
}

// ---------------- 2) sinkhorn half-iteration: vout[i] = 1/sum_j mat[i][j]*vin[j]
__device__ __forceinline__ void rowsum_recip(const float* __restrict__ mat,
                                             const float* __restrict__ vin,
                                             float* __restrict__ vout) {
    int row = blockIdx.x;
    const float* mr = mat + row * ND;
    float s = 0.f;
#pragma unroll 8
    for (int j = threadIdx.x; j < ND; j += 128) s += mr[j] * vin[j];
#pragma unroll
    for (int off = 16; off; off >>= 1) s += __shfl_xor_sync(0xffffffffu, s, off);
    __shared__ float ws[4];
    if ((threadIdx.x & 31) == 0) ws[threadIdx.x >> 5] = s;
    __syncthreads();
    if (threadIdx.x == 0) vout[row] = 1.0f / (ws[0] + ws[1] + ws[2] + ws[3]);
}
__global__ __launch_bounds__(128) void row_update_kernel() { rowsum_recip(g_P,  g_c, g_r); }
__global__ __launch_bounds__(128) void col_update_kernel() { rowsum_recip(g_Pt, g_r, g_c); }

// ---------------- 3) per-block W sinkhorn (64x64 in smem) fused with x_local -
__global__ __launch_bounds__(256) void w_xlocal_kernel(const float* __restrict__ W1,
                                                       const float* __restrict__ WV,
                                                       const float* __restrict__ x) {
    __shared__ float Pw[64][65];
    __shared__ float Xs[64][65];
    __shared__ float rw[64], cw[64];
    __shared__ float w1s[8];

    int n = blockIdx.x;
    int t = threadIdx.x;

    if (t < 8) w1s[t] = W1[n * 8 + t];
    if (t >= 64 && t < 128) cw[t - 64] = 1.0f;
    __syncthreads();

    // W_logits[n] = sum_c W1[n,c]*WV[c]; Pw = exp(5*logits)
#pragma unroll 4
    for (int e = t; e < 4096; e += 256) {
        float acc = 0.f;
#pragma unroll
        for (int cc = 0; cc < 8; cc++) acc += w1s[cc] * WV[cc * 4096 + e];
        Pw[e >> 6][e & 63] = expf(5.0f * acc);
    }
    // load x tile for this n: Xs[b][i] = x[b, n*64+i]
#pragma unroll 4
    for (int e = t; e < 4096; e += 256) {
        int b = e >> 6, i = e & 63;
        Xs[b][i] = x[b * 65536 + n * 64 + i];
    }
    __syncthreads();

    // linear-domain sinkhorn: 64 rows x 4 lanes each
    int ri = t >> 2, l4 = t & 3;
#pragma unroll 1
    for (int it = 0; it < NITER; it++) {
        float s = 0.f;
#pragma unroll
        for (int j = l4; j < 64; j += 4) s += Pw[ri][j] * cw[j];
        s += __shfl_xor_sync(0xffffffffu, s, 1);
        s += __shfl_xor_sync(0xffffffffu, s, 2);
        if (l4 == 0) rw[ri] = 1.0f / s;
        __syncthreads();
        float s2 = 0.f;
#pragma unroll
        for (int i2 = l4; i2 < 64; i2 += 4) s2 += Pw[i2][ri] * rw[i2];
        s2 += __shfl_xor_sync(0xffffffffu, s2, 1);
        s2 += __shfl_xor_sync(0xffffffffu, s2, 2);
        if (l4 == 0) cw[ri] = 1.0f / s2;
        __syncthreads();
    }

    // finalize W in place: Pw[i][o] *= rw[i]*cw[o]
#pragma unroll 4
    for (int e = t; e < 4096; e += 256)
        Pw[e >> 6][e & 63] *= rw[e >> 6] * cw[e & 63];
    __syncthreads();

    // xl[b][o] = c[n] * sum_i Xs[b][i]*Pw[i][o]
    int b = t >> 2;
    int o0 = (t & 3) * 16;
    float acc[16];
#pragma unroll
    for (int k = 0; k < 16; k++) acc[k] = 0.f;
#pragma unroll 4
    for (int i = 0; i < 64; i++) {
        float xv = Xs[b][i];
#pragma unroll
        for (int k = 0; k < 16; k++) acc[k] += xv * Pw[i][o0 + k];
    }
    float cn = g_c[n];
    float* dst = &g_XL[n * BO + b * 64 + o0];
#pragma unroll
    for (int k = 0; k < 16; k += 4) {
        float4 v = make_float4(acc[k] * cn, acc[k + 1] * cn, acc[k + 2] * cn, acc[k + 3] * cn);
        *(float4*)(dst + k) = v;
    }
}

// ---------------- 4) GEMM: out[b,m,o] = r[m] * sum_n P[m,n]*XL[n][b*64+o] ----
#define BM 128
#define BN 128
#define BK 8
__global__ __launch_bounds__(256) void gemm_kernel(float* __restrict__ out) {
    __shared__ float As[BK][BM];
    __shared__ float Bs[BK][BN];
    int t = threadIdx.x;
    int m0 = blockIdx.y * BM;
    int n0 = blockIdx.x * BN;
    int tm = t >> 4, tn = t & 15;

    float acc[8][8];
#pragma unroll
    for (int i = 0; i < 8; i++)
#pragma unroll
        for (int j = 0; j < 8; j++) acc[i][j] = 0.f;

    int arow = t >> 1, akq = (t & 1) * 4;       // A tile: 128 rows x 8 k
    int brow = t >> 5, bcol = (t & 31) * 4;     // B tile: 8 rows x 128 cols

    for (int k0 = 0; k0 < ND; k0 += BK) {
        float4 av = *(const float4*)&g_P[(m0 + arow) * ND + k0 + akq];
        float4 bv = *(const float4*)&g_XL[(k0 + brow) * BO + n0 + bcol];
        __syncthreads();
        As[akq + 0][arow] = av.x;
        As[akq + 1][arow] = av.y;
        As[akq + 2][arow] = av.z;
        As[akq + 3][arow] = av.w;
        *(float4*)&Bs[brow][bcol] = bv;
        __syncthreads();
#pragma unroll
        for (int kk = 0; kk < BK; kk++) {
            float a[8], b[8];
            *(float4*)(a)     = *(float4*)&As[kk][tm * 8];
            *(float4*)(a + 4) = *(float4*)&As[kk][tm * 8 + 4];
            *(float4*)(b)     = *(float4*)&Bs[kk][tn * 8];
            *(float4*)(b + 4) = *(float4*)&Bs[kk][tn * 8 + 4];
#pragma unroll
            for (int i = 0; i < 8; i++)
#pragma unroll
                for (int j = 0; j < 8; j++) acc[i][j] += a[i] * b[j];
        }
    }

    int bo0 = n0 + tn * 8;
    int bb = bo0 >> 6, oo = bo0 & 63;
#pragma unroll
    for (int i = 0; i < 8; i++) {
        int m = m0 + tm * 8 + i;
        float rv = g_r[m];
        float* dst = &out[bb * 65536 + m * 64 + oo];
        float4 v0 = make_float4(acc[i][0] * rv, acc[i][1] * rv, acc[i][2] * rv, acc[i][3] * rv);
        float4 v1 = make_float4(acc[i][4] * rv, acc[i][5] * rv, acc[i][6] * rv, acc[i][7] * rv);
        *(float4*)(dst)     = v0;
        *(float4*)(dst + 4) = v1;
    }
}

// ---------------- launch ----------------
extern "C" void kernel_launch(void* const* d_in, const int* in_sizes, int n_in,
                              void* d_out, int out_size) {
    const float* x        = (const float*)d_in[0];
    const float* A_logits = (const float*)d_in[1];
    const float* W1       = (const float*)d_in[2];
    const float* WV       = (const float*)d_in[3];
    float* out = (float*)d_out;

    dim3 tb(32, 8);
    exp_T_kernel<<<dim3(32, 32), tb>>>(A_logits);
    init_c_kernel<<<4, 256>>>();
    for (int it = 0; it < NITER; it++) {
        row_update_kernel<<<ND, 128>>>();
        col_update_kernel<<<ND, 128>>>();
    }
    w_xlocal_kernel<<<ND, 256>>>(W1, WV, x);
    gemm_kernel<<<dim3(BO / BN, ND / BM), 256>>>(out);
}

// round 4
// speedup vs baseline: 1.7638x; 1.7638x over previous
#include <cuda_runtime.h>
#include <cuda_bf16.h>
#include <cstdint>
#include <cstddef>

// Problem dims (fixed by dataset)
#define ND 1024   // N
#define KD 64     // K
#define BD 64     // batch
#define BO 4096   // B*K
#define NITER 20
#define SK_CTAS 128

// ---------------- scratch (device globals; no runtime alloc) ----------------
__device__ float g_P [ND * ND];             // exp(A_logits/T)
__device__ float g_Pt[ND * ND];             // transpose of g_P
__device__ float g_r [ND];                  // row scalings
__device__ float g_c [ND];                  // col scalings
__device__ __nv_bfloat16 g_Ph[ND * ND];     // hi bf16 of P   (K-major)
__device__ __nv_bfloat16 g_Pl[ND * ND];     // lo bf16 of P
__device__ __nv_bfloat16 g_XLh[ND * BO];    // hi bf16 of c[n]*x_local, [n][b*64+o]
__device__ __nv_bfloat16 g_XLl[ND * BO];    // lo bf16
__device__ unsigned g_cnt;                  // grid barrier counter

// ---------------- helpers ----------------
__device__ __forceinline__ uint32_t smem_u32(const void* p) {
    uint32_t a;
    asm("{ .reg .u64 t; cvta.to.shared.u64 t, %1; cvt.u32.u64 %0, t; }" : "=r"(a) : "l"(p));
    return a;
}

#define LDSM4(r0, r1, r2, r3, a) \
    asm volatile("ldmatrix.sync.aligned.m8n8.x4.shared.b16 {%0,%1,%2,%3}, [%4];" \
                 : "=r"(r0), "=r"(r1), "=r"(r2), "=r"(r3) : "r"(a))
#define LDSM4T(r0, r1, r2, r3, a) \
    asm volatile("ldmatrix.sync.aligned.m8n8.x4.trans.shared.b16 {%0,%1,%2,%3}, [%4];" \
                 : "=r"(r0), "=r"(r1), "=r"(r2), "=r"(r3) : "r"(a))
#define MMA16816(C, A, b0, b1) \
    asm volatile("mma.sync.aligned.m16n8k16.row.col.f32.bf16.bf16.f32 " \
                 "{%0,%1,%2,%3}, {%4,%5,%6,%7}, {%8,%9}, {%0,%1,%2,%3};" \
                 : "+f"(C[0]), "+f"(C[1]), "+f"(C[2]), "+f"(C[3]) \
                 : "r"(A[0]), "r"(A[1]), "r"(A[2]), "r"(A[3]), "r"(b0), "r"(b1))

// ---------------- 1) P = exp(5*L), transpose, bf16 hi/lo planes ----------
__global__ __launch_bounds__(256) void exp_T_kernel(const float* __restrict__ L) {
    __shared__ float tile[32][33];
    int bx = blockIdx.x * 32, by = blockIdx.y * 32;
    int tx = threadIdx.x, ty = threadIdx.y;   // 32 x 8
#pragma unroll
    for (int r0 = 0; r0 < 32; r0 += 8) {
        int idx = (by + ty + r0) * ND + bx + tx;
        float v = expf(5.0f * L[idx]);
        g_P[idx] = v;
        __nv_bfloat16 h = __float2bfloat16(v);
        g_Ph[idx] = h;
        g_Pl[idx] = __float2bfloat16(v - __bfloat162float(h));
        tile[ty + r0][tx] = v;
    }
    __syncthreads();
#pragma unroll
    for (int r0 = 0; r0 < 32; r0 += 8)
        g_Pt[(bx + ty + r0) * ND + by + tx] = tile[tx][ty + r0];
}

__global__ void init_kernel() {
    int i = blockIdx.x * 256 + threadIdx.x;
    if (i < ND) g_c[i] = 1.0f;
    if (i == 0) g_cnt = 0u;
}

// ---------------- 2) persistent sinkhorn: 128 CTAs, 1 warp per row ----------
__device__ __forceinline__ void grid_bar(unsigned target) {
    __syncthreads();
    if (threadIdx.x == 0) {
        __threadfence();
        atomicAdd(&g_cnt, 1u);
        while (*((volatile unsigned*)&g_cnt) < target) { }
    }
    __syncthreads();
}

__global__ __launch_bounds__(256) void sinkhorn_kernel() {
    __shared__ float vs[ND];
    int tid = threadIdx.x;
    int lane = tid & 31;
    int row = blockIdx.x * 8 + (tid >> 5);
    const float* __restrict__ Pr  = g_P  + (size_t)row * ND;
    const float* __restrict__ Ptr = g_Pt + (size_t)row * ND;

    unsigned target = SK_CTAS;
    for (int it = 0; it < NITER; it++) {
        // r = 1 / (P c)
        for (int i = tid; i < ND; i += 256) vs[i] = __ldcg(&g_c[i]);
        __syncthreads();
        float s = 0.f;
#pragma unroll 8
        for (int k = 0; k < 32; k++) s += Pr[lane + 32 * k] * vs[lane + 32 * k];
#pragma unroll
        for (int o = 16; o; o >>= 1) s += __shfl_xor_sync(0xffffffffu, s, o);
        if (lane == 0) g_r[row] = 1.0f / s;
        grid_bar(target); target += SK_CTAS;

        // c = 1 / (P^T r)
        for (int i = tid; i < ND; i += 256) vs[i] = __ldcg(&g_r[i]);
        __syncthreads();
        float s2 = 0.f;
#pragma unroll 8
        for (int k = 0; k < 32; k++) s2 += Ptr[lane + 32 * k] * vs[lane + 32 * k];
#pragma unroll
        for (int o = 16; o; o >>= 1) s2 += __shfl_xor_sync(0xffffffffu, s2, o);
        if (lane == 0) g_c[row] = 1.0f / s2;
        grid_bar(target); target += SK_CTAS;
    }
}

// ---------------- 3) per-block W sinkhorn fused with x_local (bf16 hi/lo out)
__global__ __launch_bounds__(256) void w_xlocal_kernel(const float* __restrict__ W1,
                                                       const float* __restrict__ WV,
                                                       const float* __restrict__ x) {
    __shared__ float Pw[64][65];
    __shared__ float Xs[64][65];
    __shared__ float rw[64], cw[64];
    __shared__ float w1s[8];

    int n = blockIdx.x;
    int t = threadIdx.x;

    if (t < 8) w1s[t] = W1[n * 8 + t];
    if (t >= 64 && t < 128) cw[t - 64] = 1.0f;
    __syncthreads();

#pragma unroll 4
    for (int e = t; e < 4096; e += 256) {
        float acc = 0.f;
#pragma unroll
        for (int cc = 0; cc < 8; cc++) acc += w1s[cc] * WV[cc * 4096 + e];
        Pw[e >> 6][e & 63] = expf(5.0f * acc);
    }
#pragma unroll 4
    for (int e = t; e < 4096; e += 256) {
        int b = e >> 6, i = e & 63;
        Xs[b][i] = x[b * 65536 + n * 64 + i];
    }
    __syncthreads();

    int ri = t >> 2, l4 = t & 3;
#pragma unroll 1
    for (int it = 0; it < NITER; it++) {
        float s = 0.f;
#pragma unroll
        for (int j = l4; j < 64; j += 4) s += Pw[ri][j] * cw[j];
        s += __shfl_xor_sync(0xffffffffu, s, 1);
        s += __shfl_xor_sync(0xffffffffu, s, 2);
        if (l4 == 0) rw[ri] = 1.0f / s;
        __syncthreads();
        float s2 = 0.f;
#pragma unroll
        for (int i2 = l4; i2 < 64; i2 += 4) s2 += Pw[i2][ri] * rw[i2];
        s2 += __shfl_xor_sync(0xffffffffu, s2, 1);
        s2 += __shfl_xor_sync(0xffffffffu, s2, 2);
        if (l4 == 0) cw[ri] = 1.0f / s2;
        __syncthreads();
    }

#pragma unroll 4
    for (int e = t; e < 4096; e += 256)
        Pw[e >> 6][e & 63] *= rw[e >> 6] * cw[e & 63];
    __syncthreads();

    int b = t >> 2;
    int o0 = (t & 3) * 16;
    float acc[16];
#pragma unroll
    for (int k = 0; k < 16; k++) acc[k] = 0.f;
#pragma unroll 4
    for (int i = 0; i < 64; i++) {
        float xv = Xs[b][i];
#pragma unroll
        for (int k = 0; k < 16; k++) acc[k] += xv * Pw[i][o0 + k];
    }
    float cn = g_c[n];
    __nv_bfloat16 hh[16], ll[16];
#pragma unroll
    for (int k = 0; k < 16; k++) {
        float v = acc[k] * cn;
        hh[k] = __float2bfloat16(v);
        ll[k] = __float2bfloat16(v - __bfloat162float(hh[k]));
    }
    __nv_bfloat16* dh = &g_XLh[n * BO + b * 64 + o0];
    __nv_bfloat16* dl = &g_XLl[n * BO + b * 64 + o0];
    *(uint4*)(dh)     = *(uint4*)(hh);
    *(uint4*)(dh + 8) = *(uint4*)(hh + 8);
    *(uint4*)(dl)     = *(uint4*)(ll);
    *(uint4*)(dl + 8) = *(uint4*)(ll + 8);
}

// ---------------- 4) mma.sync bf16 GEMM (hi/lo 3-product split) ----------------
// out[b*65536+m*64+o] = r[m] * sum_n P[m,n]*XL[n][j],  j = b*64+o
// CTA tile 128(m) x 128(j) x 32(k); 8 warps, warp tile 64x32.
#define A_LD 40     // smem row pitch (halves) for A tiles
#define B_LD 136    // smem row pitch (halves) for B tiles

__global__ __launch_bounds__(256) void gemm_mma_kernel(float* __restrict__ out) {
    __shared__ __align__(16) __nv_bfloat16 sAh[128 * A_LD];
    __shared__ __align__(16) __nv_bfloat16 sAl[128 * A_LD];
    __shared__ __align__(16) __nv_bfloat16 sBh[32 * B_LD];
    __shared__ __align__(16) __nv_bfloat16 sBl[32 * B_LD];

    const int tid  = threadIdx.x;
    const int lane = tid & 31;
    const int w    = tid >> 5;
    const int m0   = blockIdx.y * 128;
    const int j0   = blockIdx.x * 128;
    const int wm   = (w >> 2) * 64;
    const int wj   = (w & 3) * 32;

    // loader indexing: A plane = 512 uint4 (2/thread), B plane = 512 uint4 (2/thread)
    const int ar = tid >> 2, ag = (tid & 3) * 8;    // A rows ar, ar+64; halves col ag
    const int br = tid >> 4, bg = (tid & 15) * 8;   // B rows br, br+16; halves col bg

    float acc[4][4][4];
#pragma unroll
    for (int i = 0; i < 4; i++)
#pragma unroll
        for (int j = 0; j < 4; j++)
#pragma unroll
            for (int k = 0; k < 4; k++) acc[i][j][k] = 0.f;

    const uint32_t uAh = smem_u32(sAh), uAl = smem_u32(sAl);
    const uint32_t uBh = smem_u32(sBh), uBl = smem_u32(sBl);

    // chunk 0 direct to smem
    *(uint4*)&sAh[ar * A_LD + ag]        = *(const uint4*)&g_Ph[(size_t)(m0 + ar) * ND + ag];
    *(uint4*)&sAh[(ar + 64) * A_LD + ag] = *(const uint4*)&g_Ph[(size_t)(m0 + ar + 64) * ND + ag];
    *(uint4*)&sAl[ar * A_LD + ag]        = *(const uint4*)&g_Pl[(size_t)(m0 + ar) * ND + ag];
    *(uint4*)&sAl[(ar + 64) * A_LD + ag] = *(const uint4*)&g_Pl[(size_t)(m0 + ar + 64) * ND + ag];
    *(uint4*)&sBh[br * B_LD + bg]        = *(const uint4*)&g_XLh[(size_t)br * BO + j0 + bg];
    *(uint4*)&sBh[(br + 16) * B_LD + bg] = *(const uint4*)&g_XLh[(size_t)(br + 16) * BO + j0 + bg];
    *(uint4*)&sBl[br * B_LD + bg]        = *(const uint4*)&g_XLl[(size_t)br * BO + j0 + bg];
    *(uint4*)&sBl[(br + 16) * B_LD + bg] = *(const uint4*)&g_XLl[(size_t)(br + 16) * BO + j0 + bg];
    __syncthreads();

    for (int c = 0; c < 32; c++) {
        uint4 pf[8];
        if (c < 31) {
            int k0 = (c + 1) * 32;
            pf[0] = *(const uint4*)&g_Ph[(size_t)(m0 + ar) * ND + k0 + ag];
            pf[1] = *(const uint4*)&g_Ph[(size_t)(m0 + ar + 64) * ND + k0 + ag];
            pf[2] = *(const uint4*)&g_Pl[(size_t)(m0 + ar) * ND + k0 + ag];
            pf[3] = *(const uint4*)&g_Pl[(size_t)(m0 + ar + 64) * ND + k0 + ag];
            pf[4] = *(const uint4*)&g_XLh[(size_t)(k0 + br) * BO + j0 + bg];
            pf[5] = *(const uint4*)&g_XLh[(size_t)(k0 + br + 16) * BO + j0 + bg];
            pf[6] = *(const uint4*)&g_XLl[(size_t)(k0 + br) * BO + j0 + bg];
            pf[7] = *(const uint4*)&g_XLl[(size_t)(k0 + br + 16) * BO + j0 + bg];
        }

#pragma unroll
        for (int s = 0; s < 2; s++) {
            uint32_t bh[8], bl[8];
            const uint32_t boff = ((s * 16 + (lane & 15)) * B_LD + wj + (lane >> 4) * 8) * 2;
            LDSM4T(bh[0], bh[1], bh[2], bh[3], uBh + boff);
            LDSM4T(bh[4], bh[5], bh[6], bh[7], uBh + boff + 32);
            LDSM4T(bl[0], bl[1], bl[2], bl[3], uBl + boff);
            LDSM4T(bl[4], bl[5], bl[6], bl[7], uBl + boff + 32);
#pragma unroll
            for (int mi = 0; mi < 4; mi++) {
                uint32_t ah[4], al[4];
                const uint32_t aoff =
                    ((wm + mi * 16 + (lane & 15)) * A_LD + s * 16 + (lane >> 4) * 8) * 2;
                LDSM4(ah[0], ah[1], ah[2], ah[3], uAh + aoff);
                LDSM4(al[0], al[1], al[2], al[3], uAl + aoff);
#pragma unroll
                for (int nj = 0; nj < 4; nj++) {
                    const int bi = (nj >> 1) * 4 + (nj & 1) * 2;
                    MMA16816(acc[mi][nj], ah, bh[bi], bh[bi + 1]);
                    MMA16816(acc[mi][nj], ah, bl[bi], bl[bi + 1]);
                    MMA16816(acc[mi][nj], al, bh[bi], bh[bi + 1]);
                }
            }
        }
        __syncthreads();
        if (c < 31) {
            *(uint4*)&sAh[ar * A_LD + ag]        = pf[0];
            *(uint4*)&sAh[(ar + 64) * A_LD + ag] = pf[1];
            *(uint4*)&sAl[ar * A_LD + ag]        = pf[2];
            *(uint4*)&sAl[(ar + 64) * A_LD + ag] = pf[3];
            *(uint4*)&sBh[br * B_LD + bg]        = pf[4];
            *(uint4*)&sBh[(br + 16) * B_LD + bg] = pf[5];
            *(uint4*)&sBl[br * B_LD + bg]        = pf[6];
            *(uint4*)&sBl[(br + 16) * B_LD + bg] = pf[7];
            __syncthreads();
        }
    }

    // epilogue: scale by r[m], scatter j -> (b, o)
    const int mrow = lane >> 2;
    const int jc   = (lane & 3) * 2;
#pragma unroll
    for (int mi = 0; mi < 4; mi++) {
        const int mA = m0 + wm + mi * 16 + mrow;
        const int mB = mA + 8;
        const float rA = g_r[mA];
        const float rB = g_r[mB];
#pragma unroll
        for (int nj = 0; nj < 4; nj++) {
            const int j = j0 + wj + nj * 8 + jc;
            const int b = j >> 6, o = j & 63;
            float* dA = out + (size_t)b * 65536 + mA * 64 + o;
            float* dB = out + (size_t)b * 65536 + mB * 64 + o;
            *(float2*)dA = make_float2(acc[mi][nj][0] * rA, acc[mi][nj][1] * rA);
            *(float2*)dB = make_float2(acc[mi][nj][2] * rB, acc[mi][nj][3] * rB);
        }
    }
}

// ---------------- launch ----------------
extern "C" void kernel_launch(void* const* d_in, const int* in_sizes, int n_in,
                              void* d_out, int out_size) {
    const float* x        = (const float*)d_in[0];
    const float* A_logits = (const float*)d_in[1];
    const float* W1       = (const float*)d_in[2];
    const float* WV       = (const float*)d_in[3];
    float* out = (float*)d_out;

    dim3 tb(32, 8);
    exp_T_kernel<<<dim3(32, 32), tb>>>(A_logits);
    init_kernel<<<4, 256>>>();
    sinkhorn_kernel<<<SK_CTAS, 256>>>();
    w_xlocal_kernel<<<ND, 256>>>(W1, WV, x);
    gemm_mma_kernel<<<dim3(BO / 128, ND / 128), 256>>>(out);
}

// round 5
// speedup vs baseline: 2.1783x; 1.2350x over previous
#include <cuda_runtime.h>
#include <cuda_bf16.h>
#include <cstdint>
#include <cstddef>

// Problem dims (fixed by dataset)
#define ND 1024   // N
#define KD 64     // K
#define BD 64     // batch
#define BO 4096   // B*K
#define NITER 20
#define SK_CTAS 128

// ---------------- scratch (device globals; no runtime alloc) ----------------
__device__ float g_P [ND * ND];             // exp(A_logits/T)
__device__ float g_Pt[ND * ND];             // transpose of g_P
__device__ float g_r [ND];                  // row scalings
__device__ float g_c [ND];                  // col scalings
__device__ __nv_bfloat16 g_Ph[ND * ND];     // hi bf16 of P   (K-major)
__device__ __nv_bfloat16 g_Pl[ND * ND];     // lo bf16 of P
__device__ __nv_bfloat16 g_XLh[ND * BO];    // hi bf16 of c[n]*x_local, [n][b*64+o]
__device__ __nv_bfloat16 g_XLl[ND * BO];    // lo bf16
__device__ unsigned g_cnt;                  // grid barrier counter

// ---------------- helpers ----------------
__device__ __forceinline__ uint32_t smem_u32(const void* p) {
    uint32_t a;
    asm("{ .reg .u64 t; cvta.to.shared.u64 t, %1; cvt.u32.u64 %0, t; }" : "=r"(a) : "l"(p));
    return a;
}

#define LDSM4(r0, r1, r2, r3, a) \
    asm volatile("ldmatrix.sync.aligned.m8n8.x4.shared.b16 {%0,%1,%2,%3}, [%4];" \
                 : "=r"(r0), "=r"(r1), "=r"(r2), "=r"(r3) : "r"(a))
#define LDSM4T(r0, r1, r2, r3, a) \
    asm volatile("ldmatrix.sync.aligned.m8n8.x4.trans.shared.b16 {%0,%1,%2,%3}, [%4];" \
                 : "=r"(r0), "=r"(r1), "=r"(r2), "=r"(r3) : "r"(a))
#define MMA16816(C, A, b0, b1) \
    asm volatile("mma.sync.aligned.m16n8k16.row.col.f32.bf16.bf16.f32 " \
                 "{%0,%1,%2,%3}, {%4,%5,%6,%7}, {%8,%9}, {%0,%1,%2,%3};" \
                 : "+f"(C[0]), "+f"(C[1]), "+f"(C[2]), "+f"(C[3]) \
                 : "r"(A[0]), "r"(A[1]), "r"(A[2]), "r"(A[3]), "r"(b0), "r"(b1))

// ---------------- 1) P = exp(5*L), transpose, bf16 hi/lo planes ----------
__global__ __launch_bounds__(256) void exp_T_kernel(const float* __restrict__ L) {
    __shared__ float tile[32][33];
    int bx = blockIdx.x * 32, by = blockIdx.y * 32;
    int tx = threadIdx.x, ty = threadIdx.y;   // 32 x 8
#pragma unroll
    for (int r0 = 0; r0 < 32; r0 += 8) {
        int idx = (by + ty + r0) * ND + bx + tx;
        float v = __expf(5.0f * L[idx]);
        g_P[idx] = v;
        __nv_bfloat16 h = __float2bfloat16(v);
        g_Ph[idx] = h;
        g_Pl[idx] = __float2bfloat16(v - __bfloat162float(h));
        tile[ty + r0][tx] = v;
    }
    __syncthreads();
#pragma unroll
    for (int r0 = 0; r0 < 32; r0 += 8)
        g_Pt[(bx + ty + r0) * ND + by + tx] = tile[tx][ty + r0];
}

__global__ void init_kernel() {
    int i = blockIdx.x * 256 + threadIdx.x;
    if (i < ND) g_c[i] = 1.0f;
    if (i == 0) g_cnt = 0u;
}

// ---------------- 2) persistent sinkhorn: 128 CTAs, 1 warp per row ----------
__device__ __forceinline__ void grid_bar(unsigned target) {
    __syncthreads();
    if (threadIdx.x == 0) {
        __threadfence();
        atomicAdd(&g_cnt, 1u);
        while (*((volatile unsigned*)&g_cnt) < target) { }
    }
    __syncthreads();
}

__global__ __launch_bounds__(256) void sinkhorn_kernel() {
    __shared__ float vs[ND];
    int tid = threadIdx.x;
    int lane = tid & 31;
    int row = blockIdx.x * 8 + (tid >> 5);
    const float* __restrict__ Pr  = g_P  + (size_t)row * ND;
    const float* __restrict__ Ptr = g_Pt + (size_t)row * ND;

    unsigned target = SK_CTAS;
    for (int it = 0; it < NITER; it++) {
        for (int i = tid; i < ND; i += 256) vs[i] = __ldcg(&g_c[i]);
        __syncthreads();
        float s = 0.f;
#pragma unroll 8
        for (int k = 0; k < 32; k++) s += Pr[lane + 32 * k] * vs[lane + 32 * k];
#pragma unroll
        for (int o = 16; o; o >>= 1) s += __shfl_xor_sync(0xffffffffu, s, o);
        if (lane == 0) g_r[row] = 1.0f / s;
        grid_bar(target); target += SK_CTAS;

        for (int i = tid; i < ND; i += 256) vs[i] = __ldcg(&g_r[i]);
        __syncthreads();
        float s2 = 0.f;
#pragma unroll 8
        for (int k = 0; k < 32; k++) s2 += Ptr[lane + 32 * k] * vs[lane + 32 * k];
#pragma unroll
        for (int o = 16; o; o >>= 1) s2 += __shfl_xor_sync(0xffffffffu, s2, o);
        if (lane == 0) g_c[row] = 1.0f / s2;
        grid_bar(target); target += SK_CTAS;
    }
}

// ---------------- 3) W sinkhorn (registers) + mma epilogue -> XL bf16 hi/lo --
// 256 threads / 8 warps. warp w owns rows r = 8w + (lane>>2); lane&3 selects
// a 16-col slice kept in registers m[16].
#define WLD 72   // smem pitch in halves for 64x64 bf16 tiles (64 + 8 pad)

__global__ __launch_bounds__(256) void w_xlocal_kernel(const float* __restrict__ W1,
                                                       const float* __restrict__ WV,
                                                       const float* __restrict__ x) {
    __shared__ __align__(16) __nv_bfloat16 sWh[64 * WLD];
    __shared__ __align__(16) __nv_bfloat16 sWl[64 * WLD];
    __shared__ __align__(16) __nv_bfloat16 sXh[64 * WLD];
    __shared__ __align__(16) __nv_bfloat16 sXl[64 * WLD];
    __shared__ __align__(16) float cw[64];
    __shared__ __align__(16) float part[8][64];

    const int n    = blockIdx.x;
    const int t    = threadIdx.x;
    const int w    = t >> 5;
    const int lane = t & 31;
    const int r3   = lane >> 2;     // row within warp group (0..7)
    const int csub = lane & 3;      // 16-col slice (0..3)
    const int row  = 8 * w + r3;    // matrix row (0..63)

    if (t < 64) cw[t] = 1.0f;

    // ---- Phase A: logits (rank-8) + exp, into registers ----
    float m[16];
#pragma unroll
    for (int k = 0; k < 16; k++) m[k] = 0.f;
    {
        const float* wvp = WV + row * 64 + csub * 16;
#pragma unroll
        for (int c = 0; c < 8; c++) {
            float w1c = __ldg(&W1[n * 8 + c]);
            const float4* v = (const float4*)(wvp + c * 4096);
#pragma unroll
            for (int q = 0; q < 4; q++) {
                float4 f = v[q];
                m[q * 4 + 0] += w1c * f.x;
                m[q * 4 + 1] += w1c * f.y;
                m[q * 4 + 2] += w1c * f.z;
                m[q * 4 + 3] += w1c * f.w;
            }
        }
#pragma unroll
        for (int k = 0; k < 16; k++) m[k] = __expf(5.0f * m[k]);
    }
    __syncthreads();   // cw init visible

    // ---- Phase B: sinkhorn, matrix in registers ----
    float rw_own = 1.0f;
#pragma unroll 1
    for (int it = 0; it < NITER; it++) {
        // row pass: s = sum_j m[j] * cw[j]
        float4 c0 = *(const float4*)&cw[csub * 16];
        float4 c1 = *(const float4*)&cw[csub * 16 + 4];
        float4 c2 = *(const float4*)&cw[csub * 16 + 8];
        float4 c3 = *(const float4*)&cw[csub * 16 + 12];
        float s = m[0] * c0.x + m[1] * c0.y + m[2] * c0.z + m[3] * c0.w
                + m[4] * c1.x + m[5] * c1.y + m[6] * c1.z + m[7] * c1.w
                + m[8] * c2.x + m[9] * c2.y + m[10] * c2.z + m[11] * c2.w
                + m[12] * c3.x + m[13] * c3.y + m[14] * c3.z + m[15] * c3.w;
        s += __shfl_xor_sync(0xffffffffu, s, 1);
        s += __shfl_xor_sync(0xffffffffu, s, 2);
        rw_own = 1.0f / s;

        // col pass: partials p[k] = m[k]*rw_own, reduce over 8 rows in warp
        float p[16];
#pragma unroll
        for (int k = 0; k < 16; k++) p[k] = m[k] * rw_own;
#pragma unroll
        for (int o = 4; o <= 16; o <<= 1)
#pragma unroll
            for (int k = 0; k < 16; k++) p[k] += __shfl_xor_sync(0xffffffffu, p[k], o);
        if (r3 == 0) {
            float* pp = &part[w][csub * 16];
            *(float4*)(pp)      = make_float4(p[0], p[1], p[2], p[3]);
            *(float4*)(pp + 4)  = make_float4(p[4], p[5], p[6], p[7]);
            *(float4*)(pp + 8)  = make_float4(p[8], p[9], p[10], p[11]);
            *(float4*)(pp + 12) = make_float4(p[12], p[13], p[14], p[15]);
        }
        __syncthreads();
        if (t < 64) {
            float s2 = part[0][t] + part[1][t] + part[2][t] + part[3][t]
                     + part[4][t] + part[5][t] + part[6][t] + part[7][t];
            cw[t] = 1.0f / s2;
        }
        __syncthreads();
    }

    // ---- Phase C: finalize W -> bf16 hi/lo tiles; load X -> bf16 hi/lo ----
    {
        float4 c0 = *(const float4*)&cw[csub * 16];
        float4 c1 = *(const float4*)&cw[csub * 16 + 4];
        float4 c2 = *(const float4*)&cw[csub * 16 + 8];
        float4 c3 = *(const float4*)&cw[csub * 16 + 12];
        float cv[16] = {c0.x, c0.y, c0.z, c0.w, c1.x, c1.y, c1.z, c1.w,
                        c2.x, c2.y, c2.z, c2.w, c3.x, c3.y, c3.z, c3.w};
        __nv_bfloat162 hh[8], ll[8];
#pragma unroll
        for (int k = 0; k < 8; k++) {
            float v0 = m[2 * k] * rw_own * cv[2 * k];
            float v1 = m[2 * k + 1] * rw_own * cv[2 * k + 1];
            __nv_bfloat16 h0 = __float2bfloat16(v0);
            __nv_bfloat16 h1 = __float2bfloat16(v1);
            hh[k].x = h0; hh[k].y = h1;
            ll[k].x = __float2bfloat16(v0 - __bfloat162float(h0));
            ll[k].y = __float2bfloat16(v1 - __bfloat162float(h1));
        }
        __nv_bfloat16* dh = &sWh[row * WLD + csub * 16];
        __nv_bfloat16* dl = &sWl[row * WLD + csub * 16];
        *(uint4*)(dh)     = *(uint4*)(hh);
        *(uint4*)(dh + 8) = *(uint4*)(hh + 4);
        *(uint4*)(dl)     = *(uint4*)(ll);
        *(uint4*)(dl + 8) = *(uint4*)(ll + 4);
    }
    {
        int b = t >> 2;
        int i0 = (t & 3) * 16;
        const float* xp = x + (size_t)b * 65536 + n * 64 + i0;
        __nv_bfloat162 hh[8], ll[8];
#pragma unroll
        for (int q = 0; q < 4; q++) {
            float4 f = *(const float4*)(xp + q * 4);
            float v[4] = {f.x, f.y, f.z, f.w};
#pragma unroll
            for (int j = 0; j < 2; j++) {
                float v0 = v[2 * j], v1 = v[2 * j + 1];
                __nv_bfloat16 h0 = __float2bfloat16(v0);
                __nv_bfloat16 h1 = __float2bfloat16(v1);
                hh[q * 2 + j].x = h0; hh[q * 2 + j].y = h1;
                ll[q * 2 + j].x = __float2bfloat16(v0 - __bfloat162float(h0));
                ll[q * 2 + j].y = __float2bfloat16(v1 - __bfloat162float(h1));
            }
        }
        __nv_bfloat16* dh = &sXh[b * WLD + i0];
        __nv_bfloat16* dl = &sXl[b * WLD + i0];
        *(uint4*)(dh)     = *(uint4*)(hh);
        *(uint4*)(dh + 8) = *(uint4*)(hh + 4);
        *(uint4*)(dl)     = *(uint4*)(ll);
        *(uint4*)(dl + 8) = *(uint4*)(ll + 4);
    }
    __syncthreads();

    // ---- Phase D: XL = c[n] * X @ W via mma (3-product hi/lo) ----
    const uint32_t uXh = smem_u32(sXh), uXl = smem_u32(sXl);
    const uint32_t uWh = smem_u32(sWh), uWl = smem_u32(sWl);
    const int wm = (w >> 1) * 16;   // b-tile (rows)
    const int wn = (w & 1) * 32;    // o-tile (cols)

    float acc[4][4];
#pragma unroll
    for (int i = 0; i < 4; i++)
#pragma unroll
        for (int j = 0; j < 4; j++) acc[i][j] = 0.f;

#pragma unroll
    for (int kk = 0; kk < 4; kk++) {
        uint32_t ah[4], al[4];
        const uint32_t aoff = ((wm + (lane & 15)) * WLD + kk * 16 + (lane >> 4) * 8) * 2;
        LDSM4(ah[0], ah[1], ah[2], ah[3], uXh + aoff);
        LDSM4(al[0], al[1], al[2], al[3], uXl + aoff);
        uint32_t bh[8], bl[8];
        const uint32_t boff = ((kk * 16 + (lane & 15)) * WLD + wn + (lane >> 4) * 8) * 2;
        LDSM4T(bh[0], bh[1], bh[2], bh[3], uWh + boff);
        LDSM4T(bh[4], bh[5], bh[6], bh[7], uWh + boff + 32);
        LDSM4T(bl[0], bl[1], bl[2], bl[3], uWl + boff);
        LDSM4T(bl[4], bl[5], bl[6], bl[7], uWl + boff + 32);
#pragma unroll
        for (int nj = 0; nj < 4; nj++) {
            const int bi = (nj >> 1) * 4 + (nj & 1) * 2;
            MMA16816(acc[nj], ah, bh[bi], bh[bi + 1]);
            MMA16816(acc[nj], ah, bl[bi], bl[bi + 1]);
            MMA16816(acc[nj], al, bh[bi], bh[bi + 1]);
        }
    }

    // epilogue: scale by c[n], split hi/lo, store to g_XLh/g_XLl
    const float cn = g_c[n];
    const int rowA = wm + (lane >> 2);
    const int rowB = rowA + 8;
#pragma unroll
    for (int nj = 0; nj < 4; nj++) {
        const int o = wn + nj * 8 + (lane & 3) * 2;
        float vA0 = acc[nj][0] * cn, vA1 = acc[nj][1] * cn;
        float vB0 = acc[nj][2] * cn, vB1 = acc[nj][3] * cn;
        __nv_bfloat162 hA, lA, hB, lB;
        hA.x = __float2bfloat16(vA0); hA.y = __float2bfloat16(vA1);
        lA.x = __float2bfloat16(vA0 - __bfloat162float(hA.x));
        lA.y = __float2bfloat16(vA1 - __bfloat162float(hA.y));
        hB.x = __float2bfloat16(vB0); hB.y = __float2bfloat16(vB1);
        lB.x = __float2bfloat16(vB0 - __bfloat162float(hB.x));
        lB.y = __float2bfloat16(vB1 - __bfloat162float(hB.y));
        *(__nv_bfloat162*)&g_XLh[(size_t)n * BO + rowA * 64 + o] = hA;
        *(__nv_bfloat162*)&g_XLl[(size_t)n * BO + rowA * 64 + o] = lA;
        *(__nv_bfloat162*)&g_XLh[(size_t)n * BO + rowB * 64 + o] = hB;
        *(__nv_bfloat162*)&g_XLl[(size_t)n * BO + rowB * 64 + o] = lB;
    }
}

// ---------------- 4) mma.sync bf16 GEMM (hi/lo 3-product split) ----------------
#define A_LD 40     // smem row pitch (halves) for A tiles
#define B_LD 136    // smem row pitch (halves) for B tiles

__global__ __launch_bounds__(256) void gemm_mma_kernel(float* __restrict__ out) {
    __shared__ __align__(16) __nv_bfloat16 sAh[128 * A_LD];
    __shared__ __align__(16) __nv_bfloat16 sAl[128 * A_LD];
    __shared__ __align__(16) __nv_bfloat16 sBh[32 * B_LD];
    __shared__ __align__(16) __nv_bfloat16 sBl[32 * B_LD];

    const int tid  = threadIdx.x;
    const int lane = tid & 31;
    const int w    = tid >> 5;
    const int m0   = blockIdx.y * 128;
    const int j0   = blockIdx.x * 128;
    const int wm   = (w >> 2) * 64;
    const int wj   = (w & 3) * 32;

    const int ar = tid >> 2, ag = (tid & 3) * 8;
    const int br = tid >> 4, bg = (tid & 15) * 8;

    float acc[4][4][4];
#pragma unroll
    for (int i = 0; i < 4; i++)
#pragma unroll
        for (int j = 0; j < 4; j++)
#pragma unroll
            for (int k = 0; k < 4; k++) acc[i][j][k] = 0.f;

    const uint32_t uAh = smem_u32(sAh), uAl = smem_u32(sAl);
    const uint32_t uBh = smem_u32(sBh), uBl = smem_u32(sBl);

    *(uint4*)&sAh[ar * A_LD + ag]        = *(const uint4*)&g_Ph[(size_t)(m0 + ar) * ND + ag];
    *(uint4*)&sAh[(ar + 64) * A_LD + ag] = *(const uint4*)&g_Ph[(size_t)(m0 + ar + 64) * ND + ag];
    *(uint4*)&sAl[ar * A_LD + ag]        = *(const uint4*)&g_Pl[(size_t)(m0 + ar) * ND + ag];
    *(uint4*)&sAl[(ar + 64) * A_LD + ag] = *(const uint4*)&g_Pl[(size_t)(m0 + ar + 64) * ND + ag];
    *(uint4*)&sBh[br * B_LD + bg]        = *(const uint4*)&g_XLh[(size_t)br * BO + j0 + bg];
    *(uint4*)&sBh[(br + 16) * B_LD + bg] = *(const uint4*)&g_XLh[(size_t)(br + 16) * BO + j0 + bg];
    *(uint4*)&sBl[br * B_LD + bg]        = *(const uint4*)&g_XLl[(size_t)br * BO + j0 + bg];
    *(uint4*)&sBl[(br + 16) * B_LD + bg] = *(const uint4*)&g_XLl[(size_t)(br + 16) * BO + j0 + bg];
    __syncthreads();

    for (int c = 0; c < 32; c++) {
        uint4 pf[8];
        if (c < 31) {
            int k0 = (c + 1) * 32;
            pf[0] = *(const uint4*)&g_Ph[(size_t)(m0 + ar) * ND + k0 + ag];
            pf[1] = *(const uint4*)&g_Ph[(size_t)(m0 + ar + 64) * ND + k0 + ag];
            pf[2] = *(const uint4*)&g_Pl[(size_t)(m0 + ar) * ND + k0 + ag];
            pf[3] = *(const uint4*)&g_Pl[(size_t)(m0 + ar + 64) * ND + k0 + ag];
            pf[4] = *(const uint4*)&g_XLh[(size_t)(k0 + br) * BO + j0 + bg];
            pf[5] = *(const uint4*)&g_XLh[(size_t)(k0 + br + 16) * BO + j0 + bg];
            pf[6] = *(const uint4*)&g_XLl[(size_t)(k0 + br) * BO + j0 + bg];
            pf[7] = *(const uint4*)&g_XLl[(size_t)(k0 + br + 16) * BO + j0 + bg];
        }

#pragma unroll
        for (int s = 0; s < 2; s++) {
            uint32_t bh[8], bl[8];
            const uint32_t boff = ((s * 16 + (lane & 15)) * B_LD + wj + (lane >> 4) * 8) * 2;
            LDSM4T(bh[0], bh[1], bh[2], bh[3], uBh + boff);
            LDSM4T(bh[4], bh[5], bh[6], bh[7], uBh + boff + 32);
            LDSM4T(bl[0], bl[1], bl[2], bl[3], uBl + boff);
            LDSM4T(bl[4], bl[5], bl[6], bl[7], uBl + boff + 32);
#pragma unroll
            for (int mi = 0; mi < 4; mi++) {
                uint32_t ah[4], al[4];
                const uint32_t aoff =
                    ((wm + mi * 16 + (lane & 15)) * A_LD + s * 16 + (lane >> 4) * 8) * 2;
                LDSM4(ah[0], ah[1], ah[2], ah[3], uAh + aoff);
                LDSM4(al[0], al[1], al[2], al[3], uAl + aoff);
#pragma unroll
                for (int nj = 0; nj < 4; nj++) {
                    const int bi = (nj >> 1) * 4 + (nj & 1) * 2;
                    MMA16816(acc[mi][nj], ah, bh[bi], bh[bi + 1]);
                    MMA16816(acc[mi][nj], ah, bl[bi], bl[bi + 1]);
                    MMA16816(acc[mi][nj], al, bh[bi], bh[bi + 1]);
                }
            }
        }
        __syncthreads();
        if (c < 31) {
            *(uint4*)&sAh[ar * A_LD + ag]        = pf[0];
            *(uint4*)&sAh[(ar + 64) * A_LD + ag] = pf[1];
            *(uint4*)&sAl[ar * A_LD + ag]        = pf[2];
            *(uint4*)&sAl[(ar + 64) * A_LD + ag] = pf[3];
            *(uint4*)&sBh[br * B_LD + bg]        = pf[4];
            *(uint4*)&sBh[(br + 16) * B_LD + bg] = pf[5];
            *(uint4*)&sBl[br * B_LD + bg]        = pf[6];
            *(uint4*)&sBl[(br + 16) * B_LD + bg] = pf[7];
            __syncthreads();
        }
    }

    const int mrow = lane >> 2;
    const int jc   = (lane & 3) * 2;
#pragma unroll
    for (int mi = 0; mi < 4; mi++) {
        const int mA = m0 + wm + mi * 16 + mrow;
        const int mB = mA + 8;
        const float rA = g_r[mA];
        const float rB = g_r[mB];
#pragma unroll
        for (int nj = 0; nj < 4; nj++) {
            const int j = j0 + wj + nj * 8 + jc;
            const int b = j >> 6, o = j & 63;
            float* dA = out + (size_t)b * 65536 + mA * 64 + o;
            float* dB = out + (size_t)b * 65536 + mB * 64 + o;
            *(float2*)dA = make_float2(acc[mi][nj][0] * rA, acc[mi][nj][1] * rA);
            *(float2*)dB = make_float2(acc[mi][nj][2] * rB, acc[mi][nj][3] * rB);
        }
    }
}

// ---------------- launch ----------------
extern "C" void kernel_launch(void* const* d_in, const int* in_sizes, int n_in,
                              void* d_out, int out_size) {
    const float* x        = (const float*)d_in[0];
    const float* A_logits = (const float*)d_in[1];
    const float* W1       = (const float*)d_in[2];
    const float* WV       = (const float*)d_in[3];
    float* out = (float*)d_out;

    dim3 tb(32, 8);
    exp_T_kernel<<<dim3(32, 32), tb>>>(A_logits);
    init_kernel<<<4, 256>>>();
    sinkhorn_kernel<<<SK_CTAS, 256>>>();
    w_xlocal_kernel<<<ND, 256>>>(W1, WV, x);
    gemm_mma_kernel<<<dim3(BO / 128, ND / 128), 256>>>(out);
}

// round 7
// speedup vs baseline: 2.1904x; 1.0055x over previous
#include <cuda_runtime.h>
#include <cuda_bf16.h>
#include <cstdint>
#include <cstddef>

// Problem dims (fixed by dataset)
#define ND 1024   // N
#define KD 64     // K
#define BD 64     // batch
#define BO 4096   // B*K
#define NITER 20
#define SK_CTAS 128

// ---------------- scratch (device globals; no runtime alloc) ----------------
__device__ float g_P [ND * ND];             // exp(A_logits/T)
__device__ float g_Pt[ND * ND];             // transpose of g_P
__device__ float g_r [ND];                  // row scalings
__device__ float g_c [ND];                  // col scalings
__device__ __nv_bfloat16 g_Ph[ND * ND];     // hi bf16 of P   (K-major)
__device__ __nv_bfloat16 g_Pl[ND * ND];     // lo bf16 of P
__device__ __nv_bfloat16 g_XLh[ND * BO];    // hi bf16 of c[n]*x_local, [n][b*64+o]
__device__ __nv_bfloat16 g_XLl[ND * BO];    // lo bf16
__device__ unsigned g_cnt;                  // grid barrier counter

// ---------------- helpers ----------------
__device__ __forceinline__ uint32_t smem_u32(const void* p) {
    uint32_t a;
    asm("{ .reg .u64 t; cvta.to.shared.u64 t, %1; cvt.u32.u64 %0, t; }" : "=r"(a) : "l"(p));
    return a;
}

#define LDSM4(r0, r1, r2, r3, a) \
    asm volatile("ldmatrix.sync.aligned.m8n8.x4.shared.b16 {%0,%1,%2,%3}, [%4];" \
                 : "=r"(r0), "=r"(r1), "=r"(r2), "=r"(r3) : "r"(a))
#define LDSM4T(r0, r1, r2, r3, a) \
    asm volatile("ldmatrix.sync.aligned.m8n8.x4.trans.shared.b16 {%0,%1,%2,%3}, [%4];" \
                 : "=r"(r0), "=r"(r1), "=r"(r2), "=r"(r3) : "r"(a))
#define MMA16816(C, A, b0, b1) \
    asm volatile("mma.sync.aligned.m16n8k16.row.col.f32.bf16.bf16.f32 " \
                 "{%0,%1,%2,%3}, {%4,%5,%6,%7}, {%8,%9}, {%0,%1,%2,%3};" \
                 : "+f"(C[0]), "+f"(C[1]), "+f"(C[2]), "+f"(C[3]) \
                 : "r"(A[0]), "r"(A[1]), "r"(A[2]), "r"(A[3]), "r"(b0), "r"(b1))

// ---------------- 1) P = exp(5*L), transpose, bf16 hi/lo planes ----------
__global__ __launch_bounds__(256) void exp_T_kernel(const float* __restrict__ L) {
    __shared__ float tile[32][33];
    int bx = blockIdx.x * 32, by = blockIdx.y * 32;
    int tx = threadIdx.x, ty = threadIdx.y;   // 32 x 8
#pragma unroll
    for (int r0 = 0; r0 < 32; r0 += 8) {
        int idx = (by + ty + r0) * ND + bx + tx;
        float v = __expf(5.0f * L[idx]);
        g_P[idx] = v;
        __nv_bfloat16 h = __float2bfloat16(v);
        g_Ph[idx] = h;
        g_Pl[idx] = __float2bfloat16(v - __bfloat162float(h));
        tile[ty + r0][tx] = v;
    }
    __syncthreads();
#pragma unroll
    for (int r0 = 0; r0 < 32; r0 += 8)
        g_Pt[(bx + ty + r0) * ND + by + tx] = tile[tx][ty + r0];
}

__global__ void init_kernel() {
    int i = blockIdx.x * 256 + threadIdx.x;
    if (i < ND) g_c[i] = 1.0f;
    if (i == 0) g_cnt = 0u;
}

// ---------------- 2) persistent sinkhorn: 128 CTAs, 1 warp per row ----------
__device__ __forceinline__ void grid_bar(unsigned target) {
    __syncthreads();
    if (threadIdx.x == 0) {
        __threadfence();
        atomicAdd(&g_cnt, 1u);
        while (*((volatile unsigned*)&g_cnt) < target) { }
    }
    __syncthreads();
}

__global__ __launch_bounds__(256) void sinkhorn_kernel() {
    __shared__ float vs[ND];
    int tid = threadIdx.x;
    int lane = tid & 31;
    int row = blockIdx.x * 8 + (tid >> 5);
    const float* __restrict__ Pr  = g_P  + (size_t)row * ND;
    const float* __restrict__ Ptr = g_Pt + (size_t)row * ND;

    unsigned target = SK_CTAS;
    for (int it = 0; it < NITER; it++) {
        for (int i = tid; i < ND; i += 256) vs[i] = __ldcg(&g_c[i]);
        __syncthreads();
        float s = 0.f;
#pragma unroll 8
        for (int k = 0; k < 32; k++) s += Pr[lane + 32 * k] * vs[lane + 32 * k];
#pragma unroll
        for (int o = 16; o; o >>= 1) s += __shfl_xor_sync(0xffffffffu, s, o);
        if (lane == 0) g_r[row] = 1.0f / s;
        grid_bar(target); target += SK_CTAS;

        for (int i = tid; i < ND; i += 256) vs[i] = __ldcg(&g_r[i]);
        __syncthreads();
        float s2 = 0.f;
#pragma unroll 8
        for (int k = 0; k < 32; k++) s2 += Ptr[lane + 32 * k] * vs[lane + 32 * k];
#pragma unroll
        for (int o = 16; o; o >>= 1) s2 += __shfl_xor_sync(0xffffffffu, s2, o);
        if (lane == 0) g_c[row] = 1.0f / s2;
        grid_bar(target); target += SK_CTAS;
    }
}

// ---------------- 3) W sinkhorn (M + M^T in registers) + mma epilogue -------
// 256 threads / 8 warps. warp w owns rows r = 8w + (lane>>2); lane&3 selects
// a 16-col slice: m[16] = M[row][csub*16..], mt[16] = M^T[row][csub*16..].
#define WLD 72    // smem pitch in halves for 64x64 bf16 tiles (64 + 8 pad)
#define TLD 68    // fp32 transpose buffer pitch (272B rows: 16B-aligned)

__global__ __launch_bounds__(256) void w_xlocal_kernel(const float* __restrict__ W1,
                                                       const float* __restrict__ WV,
                                                       const float* __restrict__ x) {
    // union: fp32 transpose buffer (Phase A/B) aliases bf16 tiles (Phase C/D)
    __shared__ __align__(16) char uSmem[4 * 64 * WLD * 2];   // 36864 B
    __shared__ __align__(16) float rw[64], cw[64];

    float (*sT)[TLD] = (float (*)[TLD])uSmem;                // 64*68*4 = 17408 B
    __nv_bfloat16* sWh = (__nv_bfloat16*)uSmem;
    __nv_bfloat16* sWl = sWh + 64 * WLD;
    __nv_bfloat16* sXh = sWl + 64 * WLD;
    __nv_bfloat16* sXl = sXh + 64 * WLD;

    const int n    = blockIdx.x;
    const int t    = threadIdx.x;
    const int w    = t >> 5;
    const int lane = t & 31;
    const int r3   = lane >> 2;     // row within warp group (0..7)
    const int csub = lane & 3;      // 16-col slice (0..3)
    const int row  = 8 * w + r3;    // matrix row (0..63)

    // ---- Phase A: logits (rank-8) + exp, into registers ----
    float m[16];
#pragma unroll
    for (int k = 0; k < 16; k++) m[k] = 0.f;
    {
        const float* wvp = WV + row * 64 + csub * 16;
#pragma unroll
        for (int c = 0; c < 8; c++) {
            float w1c = __ldg(&W1[n * 8 + c]);
            const float4* v = (const float4*)(wvp + c * 4096);
#pragma unroll
            for (int q = 0; q < 4; q++) {
                float4 f = v[q];
                m[q * 4 + 0] += w1c * f.x;
                m[q * 4 + 1] += w1c * f.y;
                m[q * 4 + 2] += w1c * f.z;
                m[q * 4 + 3] += w1c * f.w;
            }
        }
#pragma unroll
        for (int k = 0; k < 16; k++) m[k] = __expf(5.0f * m[k]);
    }

    // stage M into smem, build M^T registers
    if (t < 64) cw[t] = 1.0f;
#pragma unroll
    for (int k = 0; k < 16; k += 4)
        *(float4*)&sT[row][csub * 16 + k] = make_float4(m[k], m[k + 1], m[k + 2], m[k + 3]);
    __syncthreads();
    float mt[16];
#pragma unroll
    for (int k = 0; k < 16; k++) mt[k] = sT[csub * 16 + k][row];

    // ---- Phase B: sinkhorn; both passes are register dot-products ----
#pragma unroll 1
    for (int it = 0; it < NITER; it++) {
        // r = 1/(M c)
        float s = 0.f;
#pragma unroll
        for (int k = 0; k < 16; k += 4) {
            float4 cf = *(const float4*)&cw[csub * 16 + k];
            s += m[k] * cf.x + m[k + 1] * cf.y + m[k + 2] * cf.z + m[k + 3] * cf.w;
        }
        s += __shfl_xor_sync(0xffffffffu, s, 1);
        s += __shfl_xor_sync(0xffffffffu, s, 2);
        if (csub == 0) rw[row] = 1.0f / s;
        __syncthreads();

        // c = 1/(M^T r)
        float s2 = 0.f;
#pragma unroll
        for (int k = 0; k < 16; k += 4) {
            float4 rf = *(const float4*)&rw[csub * 16 + k];
            s2 += mt[k] * rf.x + mt[k + 1] * rf.y + mt[k + 2] * rf.z + mt[k + 3] * rf.w;
        }
        s2 += __shfl_xor_sync(0xffffffffu, s2, 1);
        s2 += __shfl_xor_sync(0xffffffffu, s2, 2);
        if (csub == 0) cw[row] = 1.0f / s2;
        __syncthreads();
    }

    // ---- Phase C: finalize W -> bf16 hi/lo tiles; load X -> bf16 hi/lo ----
    {
        const float rw_own = rw[row];
        float cv[16];
#pragma unroll
        for (int k = 0; k < 16; k += 4) {
            float4 cf = *(const float4*)&cw[csub * 16 + k];
            cv[k] = cf.x; cv[k + 1] = cf.y; cv[k + 2] = cf.z; cv[k + 3] = cf.w;
        }
        __nv_bfloat162 hh[8], ll[8];
#pragma unroll
        for (int k = 0; k < 8; k++) {
            float v0 = m[2 * k] * rw_own * cv[2 * k];
            float v1 = m[2 * k + 1] * rw_own * cv[2 * k + 1];
            __nv_bfloat16 h0 = __float2bfloat16(v0);
            __nv_bfloat16 h1 = __float2bfloat16(v1);
            hh[k].x = h0; hh[k].y = h1;
            ll[k].x = __float2bfloat16(v0 - __bfloat162float(h0));
            ll[k].y = __float2bfloat16(v1 - __bfloat162float(h1));
        }
        __syncthreads();   // all mt/sT reads done before tiles overwrite uSmem
        __nv_bfloat16* dh = &sWh[row * WLD + csub * 16];
        __nv_bfloat16* dl = &sWl[row * WLD + csub * 16];
        *(uint4*)(dh)     = *(uint4*)(hh);
        *(uint4*)(dh + 8) = *(uint4*)(hh + 4);
        *(uint4*)(dl)     = *(uint4*)(ll);
        *(uint4*)(dl + 8) = *(uint4*)(ll + 4);
    }
    {
        int b = t >> 2;
        int i0 = (t & 3) * 16;
        const float* xp = x + (size_t)b * 65536 + n * 64 + i0;
        __nv_bfloat162 hh[8], ll[8];
#pragma unroll
        for (int q = 0; q < 4; q++) {
            float4 f = *(const float4*)(xp + q * 4);
            float v[4] = {f.x, f.y, f.z, f.w};
#pragma unroll
            for (int j = 0; j < 2; j++) {
                float v0 = v[2 * j], v1 = v[2 * j + 1];
                __nv_bfloat16 h0 = __float2bfloat16(v0);
                __nv_bfloat16 h1 = __float2bfloat16(v1);
                hh[q * 2 + j].x = h0; hh[q * 2 + j].y = h1;
                ll[q * 2 + j].x = __float2bfloat16(v0 - __bfloat162float(h0));
                ll[q * 2 + j].y = __float2bfloat16(v1 - __bfloat162float(h1));
            }
        }
        __nv_bfloat16* dh = &sXh[b * WLD + i0];
        __nv_bfloat16* dl = &sXl[b * WLD + i0];
        *(uint4*)(dh)     = *(uint4*)(hh);
        *(uint4*)(dh + 8) = *(uint4*)(hh + 4);
        *(uint4*)(dl)     = *(uint4*)(ll);
        *(uint4*)(dl + 8) = *(uint4*)(ll + 4);
    }
    __syncthreads();

    // ---- Phase D: XL = c[n] * X @ W via mma (3-product hi/lo) ----
    const uint32_t uXh = smem_u32(sXh), uXl = smem_u32(sXl);
    const uint32_t uWh = smem_u32(sWh), uWl = smem_u32(sWl);
    const int wm = (w >> 1) * 16;   // b-tile (rows)
    const int wn = (w & 1) * 32;    // o-tile (cols)

    float acc[4][4];
#pragma unroll
    for (int i = 0; i < 4; i++)
#pragma unroll
        for (int j = 0; j < 4; j++) acc[i][j] = 0.f;

#pragma unroll
    for (int kk = 0; kk < 4; kk++) {
        uint32_t ah[4], al[4];
        const uint32_t aoff = ((wm + (lane & 15)) * WLD + kk * 16 + (lane >> 4) * 8) * 2;
        LDSM4(ah[0], ah[1], ah[2], ah[3], uXh + aoff);
        LDSM4(al[0], al[1], al[2], al[3], uXl + aoff);
        uint32_t bh[8], bl[8];
        const uint32_t boff = ((kk * 16 + (lane & 15)) * WLD + wn + (lane >> 4) * 8) * 2;
        LDSM4T(bh[0], bh[1], bh[2], bh[3], uWh + boff);
        LDSM4T(bh[4], bh[5], bh[6], bh[7], uWh + boff + 32);
        LDSM4T(bl[0], bl[1], bl[2], bl[3], uWl + boff);
        LDSM4T(bl[4], bl[5], bl[6], bl[7], uWl + boff + 32);
#pragma unroll
        for (int nj = 0; nj < 4; nj++) {
            const int bi = (nj >> 1) * 4 + (nj & 1) * 2;
            MMA16816(acc[nj], ah, bh[bi], bh[bi + 1]);
            MMA16816(acc[nj], ah, bl[bi], bl[bi + 1]);
            MMA16816(acc[nj], al, bh[bi], bh[bi + 1]);
        }
    }

    // epilogue: scale by c[n], split hi/lo, store to g_XLh/g_XLl
    const float cn = g_c[n];
    const int rowA = wm + (lane >> 2);
    const int rowB = rowA + 8;
#pragma unroll
    for (int nj = 0; nj < 4; nj++) {
        const int o = wn + nj * 8 + (lane & 3) * 2;
        float vA0 = acc[nj][0] * cn, vA1 = acc[nj][1] * cn;
        float vB0 = acc[nj][2] * cn, vB1 = acc[nj][3] * cn;
        __nv_bfloat162 hA, lA, hB, lB;
        hA.x = __float2bfloat16(vA0); hA.y = __float2bfloat16(vA1);
        lA.x = __float2bfloat16(vA0 - __bfloat162float(hA.x));
        lA.y = __float2bfloat16(vA1 - __bfloat162float(hA.y));
        hB.x = __float2bfloat16(vB0); hB.y = __float2bfloat16(vB1);
        lB.x = __float2bfloat16(vB0 - __bfloat162float(hB.x));
        lB.y = __float2bfloat16(vB1 - __bfloat162float(hB.y));
        *(__nv_bfloat162*)&g_XLh[(size_t)n * BO + rowA * 64 + o] = hA;
        *(__nv_bfloat162*)&g_XLl[(size_t)n * BO + rowA * 64 + o] = lA;
        *(__nv_bfloat162*)&g_XLh[(size_t)n * BO + rowB * 64 + o] = hB;
        *(__nv_bfloat162*)&g_XLl[(size_t)n * BO + rowB * 64 + o] = lB;
    }
}

// ---------------- 4) mma.sync bf16 GEMM (hi/lo 3-product split) ----------------
#define A_LD 40     // smem row pitch (halves) for A tiles
#define B_LD 136    // smem row pitch (halves) for B tiles

__global__ __launch_bounds__(256) void gemm_mma_kernel(float* __restrict__ out) {
    __shared__ __align__(16) __nv_bfloat16 sAh[128 * A_LD];
    __shared__ __align__(16) __nv_bfloat16 sAl[128 * A_LD];
    __shared__ __align__(16) __nv_bfloat16 sBh[32 * B_LD];
    __shared__ __align__(16) __nv_bfloat16 sBl[32 * B_LD];

    const int tid  = threadIdx.x;
    const int lane = tid & 31;
    const int w    = tid >> 5;
    const int m0   = blockIdx.y * 128;
    const int j0   = blockIdx.x * 128;
    const int wm   = (w >> 2) * 64;
    const int wj   = (w & 3) * 32;

    const int ar = tid >> 2, ag = (tid & 3) * 8;
    const int br = tid >> 4, bg = (tid & 15) * 8;

    float acc[4][4][4];
#pragma unroll
    for (int i = 0; i < 4; i++)
#pragma unroll
        for (int j = 0; j < 4; j++)
#pragma unroll
            for (int k = 0; k < 4; k++) acc[i][j][k] = 0.f;

    const uint32_t uAh = smem_u32(sAh), uAl = smem_u32(sAl);
    const uint32_t uBh = smem_u32(sBh), uBl = smem_u32(sBl);

    *(uint4*)&sAh[ar * A_LD + ag]        = *(const uint4*)&g_Ph[(size_t)(m0 + ar) * ND + ag];
    *(uint4*)&sAh[(ar + 64) * A_LD + ag] = *(const uint4*)&g_Ph[(size_t)(m0 + ar + 64) * ND + ag];
    *(uint4*)&sAl[ar * A_LD + ag]        = *(const uint4*)&g_Pl[(size_t)(m0 + ar) * ND + ag];
    *(uint4*)&sAl[(ar + 64) * A_LD + ag] = *(const uint4*)&g_Pl[(size_t)(m0 + ar + 64) * ND + ag];
    *(uint4*)&sBh[br * B_LD + bg]        = *(const uint4*)&g_XLh[(size_t)br * BO + j0 + bg];
    *(uint4*)&sBh[(br + 16) * B_LD + bg] = *(const uint4*)&g_XLh[(size_t)(br + 16) * BO + j0 + bg];
    *(uint4*)&sBl[br * B_LD + bg]        = *(const uint4*)&g_XLl[(size_t)br * BO + j0 + bg];
    *(uint4*)&sBl[(br + 16) * B_LD + bg] = *(const uint4*)&g_XLl[(size_t)(br + 16) * BO + j0 + bg];
    __syncthreads();

    for (int c = 0; c < 32; c++) {
        uint4 pf[8];
        if (c < 31) {
            int k0 = (c + 1) * 32;
            pf[0] = *(const uint4*)&g_Ph[(size_t)(m0 + ar) * ND + k0 + ag];
            pf[1] = *(const uint4*)&g_Ph[(size_t)(m0 + ar + 64) * ND + k0 + ag];
            pf[2] = *(const uint4*)&g_Pl[(size_t)(m0 + ar) * ND + k0 + ag];
            pf[3] = *(const uint4*)&g_Pl[(size_t)(m0 + ar + 64) * ND + k0 + ag];
            pf[4] = *(const uint4*)&g_XLh[(size_t)(k0 + br) * BO + j0 + bg];
            pf[5] = *(const uint4*)&g_XLh[(size_t)(k0 + br + 16) * BO + j0 + bg];
            pf[6] = *(const uint4*)&g_XLl[(size_t)(k0 + br) * BO + j0 + bg];
            pf[7] = *(const uint4*)&g_XLl[(size_t)(k0 + br + 16) * BO + j0 + bg];
        }

#pragma unroll
        for (int s = 0; s < 2; s++) {
            uint32_t bh[8], bl[8];
            const uint32_t boff = ((s * 16 + (lane & 15)) * B_LD + wj + (lane >> 4) * 8) * 2;
            LDSM4T(bh[0], bh[1], bh[2], bh[3], uBh + boff);
            LDSM4T(bh[4], bh[5], bh[6], bh[7], uBh + boff + 32);
            LDSM4T(bl[0], bl[1], bl[2], bl[3], uBl + boff);
            LDSM4T(bl[4], bl[5], bl[6], bl[7], uBl + boff + 32);
#pragma unroll
            for (int mi = 0; mi < 4; mi++) {
                uint32_t ah[4], al[4];
                const uint32_t aoff =
                    ((wm + mi * 16 + (lane & 15)) * A_LD + s * 16 + (lane >> 4) * 8) * 2;
                LDSM4(ah[0], ah[1], ah[2], ah[3], uAh + aoff);
                LDSM4(al[0], al[1], al[2], al[3], uAl + aoff);
#pragma unroll
                for (int nj = 0; nj < 4; nj++) {
                    const int bi = (nj >> 1) * 4 + (nj & 1) * 2;
                    MMA16816(acc[mi][nj], ah, bh[bi], bh[bi + 1]);
                    MMA16816(acc[mi][nj], ah, bl[bi], bl[bi + 1]);
                    MMA16816(acc[mi][nj], al, bh[bi], bh[bi + 1]);
                }
            }
        }
        __syncthreads();
        if (c < 31) {
            *(uint4*)&sAh[ar * A_LD + ag]        = pf[0];
            *(uint4*)&sAh[(ar + 64) * A_LD + ag] = pf[1];
            *(uint4*)&sAl[ar * A_LD + ag]        = pf[2];
            *(uint4*)&sAl[(ar + 64) * A_LD + ag] = pf[3];
            *(uint4*)&sBh[br * B_LD + bg]        = pf[4];
            *(uint4*)&sBh[(br + 16) * B_LD + bg] = pf[5];
            *(uint4*)&sBl[br * B_LD + bg]        = pf[6];
            *(uint4*)&sBl[(br + 16) * B_LD + bg] = pf[7];
            __syncthreads();
        }
    }

    const int mrow = lane >> 2;
    const int jc   = (lane & 3) * 2;
#pragma unroll
    for (int mi = 0; mi < 4; mi++) {
        const int mA = m0 + wm + mi * 16 + mrow;
        const int mB = mA + 8;
        const float rA = g_r[mA];
        const float rB = g_r[mB];
#pragma unroll
        for (int nj = 0; nj < 4; nj++) {
            const int j = j0 + wj + nj * 8 + jc;
            const int b = j >> 6, o = j & 63;
            float* dA = out + (size_t)b * 65536 + mA * 64 + o;
            float* dB = out + (size_t)b * 65536 + mB * 64 + o;
            *(float2*)dA = make_float2(acc[mi][nj][0] * rA, acc[mi][nj][1] * rA);
            *(float2*)dB = make_float2(acc[mi][nj][2] * rB, acc[mi][nj][3] * rB);
        }
    }
}

// ---------------- launch ----------------
extern "C" void kernel_launch(void* const* d_in, const int* in_sizes, int n_in,
                              void* d_out, int out_size) {
    const float* x        = (const float*)d_in[0];
    const float* A_logits = (const float*)d_in[1];
    const float* W1       = (const float*)d_in[2];
    const float* WV       = (const float*)d_in[3];
    float* out = (float*)d_out;

    dim3 tb(32, 8);
    exp_T_kernel<<<dim3(32, 32), tb>>>(A_logits);
    init_kernel<<<4, 256>>>();
    sinkhorn_kernel<<<SK_CTAS, 256>>>();
    w_xlocal_kernel<<<ND, 256>>>(W1, WV, x);
    gemm_mma_kernel<<<dim3(BO / 128, ND / 128), 256>>>(out);
}